// round 6
// baseline (speedup 1.0000x reference)
#include <cuda_runtime.h>
#include <cuda_bf16.h>
#include <math.h>

#define B_    2048
#define NIN   1024
#define NH    1024
#define NOUT  512
#define NTOT  3072
#define KCAT  1536
#define T0c   2.0f
#define T1c   1.6374615061559636f   // 2/exp(0.2)

typedef unsigned long long ull;

// ---- device scratch (no runtime allocation allowed) ----
__device__ float g_A[B_ * KCAT];        // [x, s2_init] packed
__device__ float g_WH[KCAT * NH];       // [W1^T ; W2]
__device__ float g_W2T[NH * NOUT];      // W2 transposed
__device__ float g_TH[NTOT * B_];       // thresholds T*logit(u), layout [t][b]
__device__ float g_gapH[B_ * NH];       // init hidden gaps
__device__ float g_gapO[B_ * NOUT];     // init output gaps

// ---------------------------------------------------------------------------
// f32x2 helpers
// ---------------------------------------------------------------------------
__device__ __forceinline__ ull pack2f(float lo, float hi) {
    ull r;
    asm("mov.b64 %0, {%1, %2};" : "=l"(r)
        : "r"(__float_as_uint(lo)), "r"(__float_as_uint(hi)));
    return r;
}
__device__ __forceinline__ void fma2(ull& acc, ull a, ull b) {
    asm("fma.rn.f32x2 %0, %1, %2, %0;" : "+l"(acc) : "l"(a), "l"(b));
}

// ---------------------------------------------------------------------------
// Fused prep: segmented grid.
//   [0,3072)            pack_A
//   [3072,4096)         transpose W1 -> g_WH top
//   [4096,4608)         copy W2 -> g_WH bottom
//   [4608,5120)         transpose W2 -> g_W2T
//   [5120,29696)        thresholds
// ---------------------------------------------------------------------------
__global__ void __launch_bounds__(256) prep_k(
    const float* __restrict__ x, const float* __restrict__ s2i,
    const float* __restrict__ W1, const float* __restrict__ W2,
    const float* __restrict__ u)
{
    __shared__ float tile[32][33];
    int q = blockIdx.x, tid = threadIdx.x;

    if (q < 3072) {                                   // pack_A
        int idx = q * 256 + tid;
        int b = idx / 384, c = idx % 384;
        float4 v = (c < 256) ? ((const float4*)x)[(size_t)b * 256 + c]
                             : ((const float4*)s2i)[(size_t)b * 128 + (c - 256)];
        ((float4*)g_A)[idx] = v;
    } else if (q < 4096) {                            // transpose W1
        int r = q - 3072;
        int c0 = (r & 31) * 32, r0 = (r >> 5) * 32;
        int tx = tid & 31, ty = tid >> 5;             // ty 0..7
#pragma unroll
        for (int j = 0; j < 32; j += 8)
            tile[ty + j][tx] = W1[(size_t)(r0 + ty + j) * 1024 + c0 + tx];
        __syncthreads();
#pragma unroll
        for (int j = 0; j < 32; j += 8)
            g_WH[(size_t)(c0 + ty + j) * 1024 + r0 + tx] = tile[tx][ty + j];
    } else if (q < 4608) {                            // copy W2
        int idx = (q - 4096) * 256 + tid;
        ((float4*)(g_WH + 1024 * 1024))[idx] = ((const float4*)W2)[idx];
    } else if (q < 5120) {                            // transpose W2
        int r = q - 4608;
        int c0 = (r & 31) * 32, r0 = (r >> 5) * 32;   // r>>5 in 0..15
        int tx = tid & 31, ty = tid >> 5;
#pragma unroll
        for (int j = 0; j < 32; j += 8)
            tile[ty + j][tx] = W2[(size_t)(r0 + ty + j) * 1024 + c0 + tx];
        __syncthreads();
#pragma unroll
        for (int j = 0; j < 32; j += 8)
            g_W2T[(size_t)(c0 + ty + j) * 512 + r0 + tx] = tile[tx][ty + j];
    } else {                                          // thresholds
        int idx = (q - 5120) * 256 + tid;
        float T = (idx < 1536 * 2048) ? T0c : T1c;
        float uu = u[idx];
        g_TH[idx] = T * (logf(uu) - log1pf(-uu));
    }
}

// ---------------------------------------------------------------------------
// FP32 GEMM v3: C[M,N] = A[M,K] @ Bm[K,N] + bias[N]
// 128x64 tile, 256 threads, 8x4 microtile; B read as packed f32x2 col-pairs.
// Sequential-k accumulation per output -> bit-identical to prior rounds.
// ---------------------------------------------------------------------------
__global__ void __launch_bounds__(256, 2) gemm_bias_k(
    const float* __restrict__ A, const float* __restrict__ Bm,
    const float* __restrict__ bias, float* __restrict__ C,
    int M, int N, int K)
{
    __shared__ float As[16][132];   // [k][m], 128 rows
    __shared__ float Bs[16][72];    // [k][n], 64 cols, 8B-aligned rows
    int t  = threadIdx.x;
    int tx = t & 15, ty = t >> 4;                  // 16 col-groups x 16 row-groups
    int m0 = blockIdx.y * 128, n0 = blockIdx.x * 64;

    int ar = t >> 2;            // 0..63 (+64)
    int ak = (t & 3) * 4;
    int bk = t >> 4;            // 0..15
    int bc = (t & 15) * 4;

    ull acc[8][2];
#pragma unroll
    for (int i = 0; i < 8; i++) { acc[i][0] = 0ull; acc[i][1] = 0ull; }

    for (int k0 = 0; k0 < K; k0 += 16) {
        float4 a0 = *(const float4*)&A[(size_t)(m0 + ar) * K + k0 + ak];
        float4 a1 = *(const float4*)&A[(size_t)(m0 + ar + 64) * K + k0 + ak];
        float4 b0 = *(const float4*)&Bm[(size_t)(k0 + bk) * N + n0 + bc];
        As[ak + 0][ar] = a0.x; As[ak + 1][ar] = a0.y;
        As[ak + 2][ar] = a0.z; As[ak + 3][ar] = a0.w;
        As[ak + 0][ar + 64] = a1.x; As[ak + 1][ar + 64] = a1.y;
        As[ak + 2][ar + 64] = a1.z; As[ak + 3][ar + 64] = a1.w;
        *(float4*)&Bs[bk][bc] = b0;
        __syncthreads();
#pragma unroll
        for (int k = 0; k < 16; ++k) {
            float4 av0 = *(const float4*)&As[k][ty * 8];
            float4 av1 = *(const float4*)&As[k][ty * 8 + 4];
            const ull* bpp = (const ull*)&Bs[k][tx * 4];
            ull bp0 = bpp[0], bp1 = bpp[1];
            float a[8] = { av0.x, av0.y, av0.z, av0.w,
                           av1.x, av1.y, av1.z, av1.w };
#pragma unroll
            for (int i = 0; i < 8; i++) {
                ull a2 = pack2f(a[i], a[i]);
                fma2(acc[i][0], bp0, a2);
                fma2(acc[i][1], bp1, a2);
            }
        }
        __syncthreads();
    }

    float4 bv = *(const float4*)&bias[n0 + tx * 4];
    float bb[4] = { bv.x, bv.y, bv.z, bv.w };
#pragma unroll
    for (int i = 0; i < 8; i++) {
        float4 o;
        o.x = __uint_as_float((unsigned)acc[i][0]) + bb[0];
        o.y = __uint_as_float((unsigned)(acc[i][0] >> 32)) + bb[1];
        o.z = __uint_as_float((unsigned)acc[i][1]) + bb[2];
        o.w = __uint_as_float((unsigned)(acc[i][1] >> 32)) + bb[3];
        *(float4*)&C[(size_t)(m0 + ty * 8 + i) * N + n0 + tx * 4] = o;
    }
}

// ---------------------------------------------------------------------------
// Gibbs v3: 256 blocks x 256 threads, 8 chains/block, 2 CTAs/SM.
// thread t owns H units 4t..4t+3 and O units 2t..2t+1, for 8 chains,
// packed as f32x2 chain-pairs. Thresholds read from gmem (prefetched).
// smem: ids [0,3072) | ds 2 bufs x 32 units x 8 chains [3072,3584)
// ---------------------------------------------------------------------------
#define DS_OFF 3072
#define SMEM_BYTES ((3072 + 512) * 4)

__global__ void __launch_bounds__(256, 2) gibbs_k(
    const float* __restrict__ x, const float* __restrict__ s1i,
    const float* __restrict__ s2i, const float* __restrict__ W2,
    const int* __restrict__ ids, float* __restrict__ out)
{
    extern __shared__ float sm[];
    int* ids_s = (int*)sm;
    float* ds  = sm + DS_OFF;

    int tid = threadIdx.x;
    int c0  = blockIdx.x * 8;

    for (int i = tid; i < NTOT; i += 256) ids_s[i] = ids[i];

    // ---- register gaps ----
    ull rH[4][4], rO[2][4];
#pragma unroll
    for (int u = 0; u < 4; u++)
#pragma unroll
        for (int p = 0; p < 4; p++)
            rH[u][p] = pack2f(g_gapH[(size_t)(c0 + 2 * p) * NH + 4 * tid + u],
                              g_gapH[(size_t)(c0 + 2 * p + 1) * NH + 4 * tid + u]);
#pragma unroll
    for (int v = 0; v < 2; v++)
#pragma unroll
        for (int p = 0; p < 4; p++)
            rO[v][p] = pack2f(g_gapO[(size_t)(c0 + 2 * p) * NOUT + 2 * tid + v],
                              g_gapO[(size_t)(c0 + 2 * p + 1) * NOUT + 2 * tid + v]);

    unsigned sH = 0, sO = 0;
#pragma unroll
    for (int c = 0; c < 8; c++) {
#pragma unroll
        for (int u = 0; u < 4; u++)
            if (s1i[(size_t)(c0 + c) * NH + 4 * tid + u] > 0.5f)
                sH |= 1u << (u * 8 + c);
#pragma unroll
        for (int v = 0; v < 2; v++)
            if (s2i[(size_t)(c0 + c) * NOUT + 2 * tid + v] > 0.5f)
                sO |= 1u << (v * 8 + c);
    }

    // warm threshold lines
    if (tid < 40)
        asm volatile("prefetch.global.L1 [%0];"
                     :: "l"(&g_TH[(size_t)tid * B_ + c0]));
    __syncthreads();

    int pos = 0, buf = 0;
    while (pos < NTOT) {
        int n0  = ids_s[pos];
        int lay = (n0 >= NH);
        int lim = NTOT - pos;
        if (lim > 32) lim = 32;
        int r = 1;
        while (r < lim && ((ids_s[pos + r] >= NH) != 0) == (lay != 0)) r++;

        // prefetch upcoming thresholds (8..40 updates ahead)
        if (tid < 32) {
            int qf = pos + 8 + tid;
            if (qf < NTOT)
                asm volatile("prefetch.global.L1 [%0];"
                             :: "l"(&g_TH[(size_t)qf * B_ + c0]));
        }
        // prefetch this phase's weight slices
        for (int i = 0; i < r; i++) {
            int n = ids_s[pos + i];
            const float* wp = lay ? (W2 + (size_t)(n - NH) * NH + 4 * tid)
                                  : (g_W2T + (size_t)n * NOUT + 2 * tid);
            asm volatile("prefetch.global.L1 [%0];" :: "l"(wp));
        }

        float* dbase = ds + buf * 256;

        // ---- decisions (owner threads, sequential in i per owner) ----
        if (!lay) {
            for (int i = 0; i < r; i++) {
                int n = ids_s[pos + i];
                if (tid == (n >> 2)) {
                    int u = n & 3;
                    const float4* thp =
                        (const float4*)&g_TH[(size_t)(pos + i) * B_ + c0];
                    float4 t0 = __ldg(thp), t1 = __ldg(thp + 1);
                    float th8[8] = { t0.x, t0.y, t0.z, t0.w,
                                     t1.x, t1.y, t1.z, t1.w };
                    unsigned newbits = 0;
                    float dv[8];
#define DEC_H(U)                                                              \
                    {                                                         \
                        _Pragma("unroll")                                     \
                        for (int p = 0; p < 4; p++) {                         \
                            ull g = rH[U][p];                                 \
                            float glo = __uint_as_float((unsigned)g);         \
                            float ghi = __uint_as_float((unsigned)(g >> 32)); \
                            float nl = (glo > th8[2 * p])     ? 1.f : 0.f;    \
                            float nh = (ghi > th8[2 * p + 1]) ? 1.f : 0.f;    \
                            if (nl > 0.f) newbits |= 1u << (2 * p);           \
                            if (nh > 0.f) newbits |= 1u << (2 * p + 1);       \
                            dv[2 * p] = nl; dv[2 * p + 1] = nh;               \
                        }                                                     \
                    }
                    if      (u == 0) DEC_H(0)
                    else if (u == 1) DEC_H(1)
                    else if (u == 2) DEC_H(2)
                    else             DEC_H(3)
#undef DEC_H
                    unsigned oldb = (sH >> (u * 8)) & 0xFFu;
#pragma unroll
                    for (int c = 0; c < 8; c++)
                        dv[c] -= (float)((oldb >> c) & 1u);
                    sH = (sH & ~(0xFFu << (u * 8))) | (newbits << (u * 8));
                    float4* dq = (float4*)(dbase + i * 8);
                    dq[0] = make_float4(dv[0], dv[1], dv[2], dv[3]);
                    dq[1] = make_float4(dv[4], dv[5], dv[6], dv[7]);
                }
            }
        } else {
            for (int i = 0; i < r; i++) {
                int o = ids_s[pos + i] - NH;
                if (tid == (o >> 1)) {
                    int v = o & 1;
                    const float4* thp =
                        (const float4*)&g_TH[(size_t)(pos + i) * B_ + c0];
                    float4 t0 = __ldg(thp), t1 = __ldg(thp + 1);
                    float th8[8] = { t0.x, t0.y, t0.z, t0.w,
                                     t1.x, t1.y, t1.z, t1.w };
                    unsigned newbits = 0;
                    float dv[8];
#define DEC_O(V)                                                              \
                    {                                                         \
                        _Pragma("unroll")                                     \
                        for (int p = 0; p < 4; p++) {                         \
                            ull g = rO[V][p];                                 \
                            float glo = __uint_as_float((unsigned)g);         \
                            float ghi = __uint_as_float((unsigned)(g >> 32)); \
                            float nl = (glo > th8[2 * p])     ? 1.f : 0.f;    \
                            float nh = (ghi > th8[2 * p + 1]) ? 1.f : 0.f;    \
                            if (nl > 0.f) newbits |= 1u << (2 * p);           \
                            if (nh > 0.f) newbits |= 1u << (2 * p + 1);       \
                            dv[2 * p] = nl; dv[2 * p + 1] = nh;               \
                        }                                                     \
                    }
                    if (v == 0) DEC_O(0) else DEC_O(1)
#undef DEC_O
                    unsigned oldb = (sO >> (v * 8)) & 0xFFu;
#pragma unroll
                    for (int c = 0; c < 8; c++)
                        dv[c] -= (float)((oldb >> c) & 1u);
                    sO = (sO & ~(0xFFu << (v * 8))) | (newbits << (v * 8));
                    float4* dq = (float4*)(dbase + i * 8);
                    dq[0] = make_float4(dv[0], dv[1], dv[2], dv[3]);
                    dq[1] = make_float4(dv[4], dv[5], dv[6], dv[7]);
                }
            }
        }
        __syncthreads();

        // ---- apply (all threads, register FMAs) ----
        if (!lay) {
            for (int i = 0; i < r; i++) {
                int n = ids_s[pos + i];
                float2 wv = __ldg((const float2*)(g_W2T + (size_t)n * NOUT + 2 * tid));
                ull w0 = pack2f(wv.x, wv.x);
                ull w1 = pack2f(wv.y, wv.y);
                const ull* dp = (const ull*)(dbase + i * 8);
#pragma unroll
                for (int p = 0; p < 4; p++) {
                    ull d = dp[p];
                    fma2(rO[0][p], d, w0);
                    fma2(rO[1][p], d, w1);
                }
            }
        } else {
            for (int i = 0; i < r; i++) {
                int o = ids_s[pos + i] - NH;
                float4 wv = __ldg((const float4*)(W2 + (size_t)o * NH + 4 * tid));
                ull w0 = pack2f(wv.x, wv.x);
                ull w1 = pack2f(wv.y, wv.y);
                ull w2_ = pack2f(wv.z, wv.z);
                ull w3 = pack2f(wv.w, wv.w);
                const ull* dp = (const ull*)(dbase + i * 8);
#pragma unroll
                for (int p = 0; p < 4; p++) {
                    ull d = dp[p];
                    fma2(rH[0][p], d, w0);
                    fma2(rH[1][p], d, w1);
                    fma2(rH[2][p], d, w2_);
                    fma2(rH[3][p], d, w3);
                }
            }
        }
        pos += r;
        buf ^= 1;
    }

    // ---- epilogue: direct coalesced writes from registers ----
#pragma unroll
    for (int c = 0; c < 8; c++) {
        int b = c0 + c;
        size_t rb4 = (size_t)b * 640;      // float4 index of row base
        ((float4*)out)[rb4 + tid] = ((const float4*)x)[(size_t)b * 256 + tid];
        float4 s1v;
        s1v.x = (sH >> (0 * 8 + c)) & 1u ? 1.f : 0.f;
        s1v.y = (sH >> (1 * 8 + c)) & 1u ? 1.f : 0.f;
        s1v.z = (sH >> (2 * 8 + c)) & 1u ? 1.f : 0.f;
        s1v.w = (sH >> (3 * 8 + c)) & 1u ? 1.f : 0.f;
        ((float4*)out)[rb4 + 256 + tid] = s1v;
        float2 s2v;
        s2v.x = (sO >> (0 * 8 + c)) & 1u ? 1.f : 0.f;
        s2v.y = (sO >> (1 * 8 + c)) & 1u ? 1.f : 0.f;
        *(float2*)&out[(size_t)b * 2560 + 2048 + 2 * tid] = s2v;
    }
}

// ---------------------------------------------------------------------------
extern "C" void kernel_launch(void* const* d_in, const int* in_sizes, int n_in,
                              void* d_out, int out_size)
{
    const float* x   = (const float*)d_in[0];
    const float* s1i = (const float*)d_in[1];
    const float* s2i = (const float*)d_in[2];
    const float* W1  = (const float*)d_in[3];
    const float* b1  = (const float*)d_in[4];
    const float* W2  = (const float*)d_in[5];
    const float* b2  = (const float*)d_in[6];
    const float* u   = (const float*)d_in[7];
    const int*   ids = (const int*)d_in[8];
    float* out = (float*)d_out;

    float *pA, *pWH, *pW2T, *pGH, *pGO;
    cudaGetSymbolAddress((void**)&pA,   g_A);
    cudaGetSymbolAddress((void**)&pWH,  g_WH);
    cudaGetSymbolAddress((void**)&pW2T, g_W2T);
    cudaGetSymbolAddress((void**)&pGH,  g_gapH);
    cudaGetSymbolAddress((void**)&pGO,  g_gapO);

    prep_k     <<<29696, 256>>>(x, s2i, W1, W2, u);
    gemm_bias_k<<<dim3(16, 16), 256>>>(pA,  pWH,  b1, pGH, 2048, 1024, 1536);
    gemm_bias_k<<<dim3(8, 16),  256>>>(s1i, pW2T, b2, pGO, 2048, 512, 1024);

    cudaFuncSetAttribute(gibbs_k, cudaFuncAttributeMaxDynamicSharedMemorySize,
                         SMEM_BYTES);
    gibbs_k<<<256, 256, SMEM_BYTES>>>(x, s1i, s2i, W2, ids, out);
}

// round 7
// speedup vs baseline: 1.1688x; 1.1688x over previous
#include <cuda_runtime.h>
#include <cuda_bf16.h>
#include <math.h>

#define B_    2048
#define NIN   1024
#define NH    1024
#define NOUT  512
#define NTOT  3072
#define KCAT  1536
#define T0c   2.0f
#define T1c   1.6374615061559636f   // 2/exp(0.2)

typedef unsigned long long ull;

// ---- device scratch (no runtime allocation allowed) ----
__device__ float g_A[B_ * KCAT];        // [x, s2_init] packed
__device__ float g_WH[KCAT * NH];       // [W1^T ; W2]
__device__ float g_W2T[NH * NOUT];      // W2 transposed
__device__ float g_TH[NTOT * B_];       // thresholds T*logit(u), layout [t][b]
__device__ float g_gapH[B_ * NH];       // init hidden gaps
__device__ float g_gapO[B_ * NOUT];     // init output gaps

// ---------------------------------------------------------------------------
// f32x2 helpers
// ---------------------------------------------------------------------------
__device__ __forceinline__ ull pack2f(float lo, float hi) {
    ull r;
    asm("mov.b64 %0, {%1, %2};" : "=l"(r)
        : "r"(__float_as_uint(lo)), "r"(__float_as_uint(hi)));
    return r;
}
__device__ __forceinline__ void fma2(ull& acc, ull a, ull b) {
    asm("fma.rn.f32x2 %0, %1, %2, %0;" : "+l"(acc) : "l"(a), "l"(b));
}

// ---------------------------------------------------------------------------
// Fused prep: segmented grid.
// ---------------------------------------------------------------------------
__global__ void __launch_bounds__(256) prep_k(
    const float* __restrict__ x, const float* __restrict__ s2i,
    const float* __restrict__ W1, const float* __restrict__ W2,
    const float* __restrict__ u)
{
    __shared__ float tile[32][33];
    int q = blockIdx.x, tid = threadIdx.x;

    if (q < 3072) {                                   // pack_A
        int idx = q * 256 + tid;
        int b = idx / 384, c = idx % 384;
        float4 v = (c < 256) ? ((const float4*)x)[(size_t)b * 256 + c]
                             : ((const float4*)s2i)[(size_t)b * 128 + (c - 256)];
        ((float4*)g_A)[idx] = v;
    } else if (q < 4096) {                            // transpose W1
        int r = q - 3072;
        int c0 = (r & 31) * 32, r0 = (r >> 5) * 32;
        int tx = tid & 31, ty = tid >> 5;
#pragma unroll
        for (int j = 0; j < 32; j += 8)
            tile[ty + j][tx] = W1[(size_t)(r0 + ty + j) * 1024 + c0 + tx];
        __syncthreads();
#pragma unroll
        for (int j = 0; j < 32; j += 8)
            g_WH[(size_t)(c0 + ty + j) * 1024 + r0 + tx] = tile[tx][ty + j];
    } else if (q < 4608) {                            // copy W2
        int idx = (q - 4096) * 256 + tid;
        ((float4*)(g_WH + 1024 * 1024))[idx] = ((const float4*)W2)[idx];
    } else if (q < 5120) {                            // transpose W2
        int r = q - 4608;
        int c0 = (r & 31) * 32, r0 = (r >> 5) * 32;
        int tx = tid & 31, ty = tid >> 5;
#pragma unroll
        for (int j = 0; j < 32; j += 8)
            tile[ty + j][tx] = W2[(size_t)(r0 + ty + j) * 1024 + c0 + tx];
        __syncthreads();
#pragma unroll
        for (int j = 0; j < 32; j += 8)
            g_W2T[(size_t)(c0 + ty + j) * 512 + r0 + tx] = tile[tx][ty + j];
    } else {                                          // thresholds
        int idx = (q - 5120) * 256 + tid;
        float T = (idx < 1536 * 2048) ? T0c : T1c;
        float uu = u[idx];
        g_TH[idx] = T * (logf(uu) - log1pf(-uu));
    }
}

// ---------------------------------------------------------------------------
// FP32 GEMM v3: C[M,N] = A[M,K] @ Bm[K,N] + bias[N]
// 128x64 tile, 256 threads, 8x4 microtile, 2 CTAs/SM.
// ---------------------------------------------------------------------------
__global__ void __launch_bounds__(256, 2) gemm_bias_k(
    const float* __restrict__ A, const float* __restrict__ Bm,
    const float* __restrict__ bias, float* __restrict__ C,
    int M, int N, int K)
{
    __shared__ float As[16][132];
    __shared__ float Bs[16][72];
    int t  = threadIdx.x;
    int tx = t & 15, ty = t >> 4;
    int m0 = blockIdx.y * 128, n0 = blockIdx.x * 64;

    int ar = t >> 2;
    int ak = (t & 3) * 4;
    int bk = t >> 4;
    int bc = (t & 15) * 4;

    ull acc[8][2];
#pragma unroll
    for (int i = 0; i < 8; i++) { acc[i][0] = 0ull; acc[i][1] = 0ull; }

    for (int k0 = 0; k0 < K; k0 += 16) {
        float4 a0 = *(const float4*)&A[(size_t)(m0 + ar) * K + k0 + ak];
        float4 a1 = *(const float4*)&A[(size_t)(m0 + ar + 64) * K + k0 + ak];
        float4 b0 = *(const float4*)&Bm[(size_t)(k0 + bk) * N + n0 + bc];
        As[ak + 0][ar] = a0.x; As[ak + 1][ar] = a0.y;
        As[ak + 2][ar] = a0.z; As[ak + 3][ar] = a0.w;
        As[ak + 0][ar + 64] = a1.x; As[ak + 1][ar + 64] = a1.y;
        As[ak + 2][ar + 64] = a1.z; As[ak + 3][ar + 64] = a1.w;
        *(float4*)&Bs[bk][bc] = b0;
        __syncthreads();
#pragma unroll
        for (int k = 0; k < 16; ++k) {
            float4 av0 = *(const float4*)&As[k][ty * 8];
            float4 av1 = *(const float4*)&As[k][ty * 8 + 4];
            const ull* bpp = (const ull*)&Bs[k][tx * 4];
            ull bp0 = bpp[0], bp1 = bpp[1];
            float a[8] = { av0.x, av0.y, av0.z, av0.w,
                           av1.x, av1.y, av1.z, av1.w };
#pragma unroll
            for (int i = 0; i < 8; i++) {
                ull a2 = pack2f(a[i], a[i]);
                fma2(acc[i][0], bp0, a2);
                fma2(acc[i][1], bp1, a2);
            }
        }
        __syncthreads();
    }

    float4 bv = *(const float4*)&bias[n0 + tx * 4];
    float bb[4] = { bv.x, bv.y, bv.z, bv.w };
#pragma unroll
    for (int i = 0; i < 8; i++) {
        float4 o;
        o.x = __uint_as_float((unsigned)acc[i][0]) + bb[0];
        o.y = __uint_as_float((unsigned)(acc[i][0] >> 32)) + bb[1];
        o.z = __uint_as_float((unsigned)acc[i][1]) + bb[2];
        o.w = __uint_as_float((unsigned)(acc[i][1] >> 32)) + bb[3];
        *(float4*)&C[(size_t)(m0 + ty * 8 + i) * N + n0 + tx * 4] = o;
    }
}

// ---------------------------------------------------------------------------
// Gibbs v4: 256 blocks x 256 threads, 8 chains/block, 2 CTAs/SM.
// Register gaps; thresholds staged in smem; run lengths via layer bitmasks.
// smem floats: ids(ushort) [0,1536) | masks [1536,1664) | ds [1664,2176) |
//              th_s [2176, 2176+24576)
// ---------------------------------------------------------------------------
#define IDS_F   0
#define MSK_F   1536
#define DS_F    1664
#define THS_F   2176
#define SMEM_FLOATS (THS_F + NTOT * 8)
#define SMEM_BYTES  (SMEM_FLOATS * 4)

__global__ void __launch_bounds__(256, 2) gibbs_k(
    const float* __restrict__ x, const float* __restrict__ s1i,
    const float* __restrict__ s2i, const float* __restrict__ W2,
    const int* __restrict__ ids, float* __restrict__ out)
{
    extern __shared__ float sm[];
    unsigned short* ids_s = (unsigned short*)(sm + IDS_F);
    unsigned* masks = (unsigned*)(sm + MSK_F);
    float* ds   = sm + DS_F;
    float* th_s = sm + THS_F;

    int tid  = threadIdx.x;
    int wid  = tid >> 5, lane = tid & 31;
    int c0   = blockIdx.x * 8;

    // ids (ushort) + layer masks via ballot
    for (int i = tid; i < NTOT; i += 256) ids_s[i] = (unsigned short)ids[i];
    for (int g = wid; g < 96; g += 8) {
        int v = ids[g * 32 + lane];
        unsigned m = __ballot_sync(0xffffffffu, v >= NH);
        if (lane == 0) masks[g] = m;
    }
    if (tid == 0) masks[96] = 0u;

    // stage thresholds for this block's 8 chains: th_s[t*8 + c]
    for (int i = tid; i < NTOT * 2; i += 256) {
        int t = i >> 1, h = i & 1;
        ((float4*)th_s)[i] =
            *(const float4*)&g_TH[(size_t)t * B_ + c0 + 4 * h];
    }

    // ---- register gaps ----
    ull rH[4][4], rO[2][4];
#pragma unroll
    for (int u = 0; u < 4; u++)
#pragma unroll
        for (int p = 0; p < 4; p++)
            rH[u][p] = pack2f(g_gapH[(size_t)(c0 + 2 * p) * NH + 4 * tid + u],
                              g_gapH[(size_t)(c0 + 2 * p + 1) * NH + 4 * tid + u]);
#pragma unroll
    for (int v = 0; v < 2; v++)
#pragma unroll
        for (int p = 0; p < 4; p++)
            rO[v][p] = pack2f(g_gapO[(size_t)(c0 + 2 * p) * NOUT + 2 * tid + v],
                              g_gapO[(size_t)(c0 + 2 * p + 1) * NOUT + 2 * tid + v]);

    unsigned sH = 0, sO = 0;
#pragma unroll
    for (int c = 0; c < 8; c++) {
#pragma unroll
        for (int u = 0; u < 4; u++)
            if (s1i[(size_t)(c0 + c) * NH + 4 * tid + u] > 0.5f)
                sH |= 1u << (u * 8 + c);
#pragma unroll
        for (int v = 0; v < 2; v++)
            if (s2i[(size_t)(c0 + c) * NOUT + 2 * tid + v] > 0.5f)
                sO |= 1u << (v * 8 + c);
    }
    __syncthreads();

    int pos = 0, buf = 0;
    while (pos < NTOT) {
        // run length from masks (no dependent-LDS chain)
        int w = pos >> 5, off = pos & 31;
        unsigned m0 = masks[w];
        unsigned m1 = masks[w + 1];
        unsigned v = (m0 >> off) | (off ? (m1 << (32 - off)) : 0u);
        int lay = (int)(v & 1u);
        unsigned tdif = lay ? ~v : v;
        int r = tdif ? (__ffs(tdif) - 1) : 32;
        int rem = NTOT - pos;
        if (r > rem) r = rem;

        // prefetch this phase's weight slices
        for (int i = 0; i < r; i++) {
            int n = ids_s[pos + i];
            const float* wp = lay ? (W2 + (size_t)(n - NH) * NH + 4 * tid)
                                  : (g_W2T + (size_t)n * NOUT + 2 * tid);
            asm volatile("prefetch.global.L1 [%0];" :: "l"(wp));
        }

        float* dbase = ds + buf * 256;

        // ---- decisions (owner threads, th from smem) ----
        if (!lay) {
            for (int i = 0; i < r; i++) {
                int n = ids_s[pos + i];
                if (tid == (n >> 2)) {
                    int u = n & 3;
                    const float4* thp = (const float4*)&th_s[(size_t)(pos + i) * 8];
                    float4 t0 = thp[0], t1 = thp[1];
                    float th8[8] = { t0.x, t0.y, t0.z, t0.w,
                                     t1.x, t1.y, t1.z, t1.w };
                    unsigned newbits = 0;
                    float dv[8];
#define DEC_H(U)                                                              \
                    {                                                         \
                        _Pragma("unroll")                                     \
                        for (int p = 0; p < 4; p++) {                         \
                            ull g = rH[U][p];                                 \
                            float glo = __uint_as_float((unsigned)g);         \
                            float ghi = __uint_as_float((unsigned)(g >> 32)); \
                            float nl = (glo > th8[2 * p])     ? 1.f : 0.f;    \
                            float nh = (ghi > th8[2 * p + 1]) ? 1.f : 0.f;    \
                            if (nl > 0.f) newbits |= 1u << (2 * p);           \
                            if (nh > 0.f) newbits |= 1u << (2 * p + 1);       \
                            dv[2 * p] = nl; dv[2 * p + 1] = nh;               \
                        }                                                     \
                    }
                    if      (u == 0) DEC_H(0)
                    else if (u == 1) DEC_H(1)
                    else if (u == 2) DEC_H(2)
                    else             DEC_H(3)
#undef DEC_H
                    unsigned oldb = (sH >> (u * 8)) & 0xFFu;
#pragma unroll
                    for (int c = 0; c < 8; c++)
                        dv[c] -= (float)((oldb >> c) & 1u);
                    sH = (sH & ~(0xFFu << (u * 8))) | (newbits << (u * 8));
                    float4* dq = (float4*)(dbase + i * 8);
                    dq[0] = make_float4(dv[0], dv[1], dv[2], dv[3]);
                    dq[1] = make_float4(dv[4], dv[5], dv[6], dv[7]);
                }
            }
        } else {
            for (int i = 0; i < r; i++) {
                int o = ids_s[pos + i] - NH;
                if (tid == (o >> 1)) {
                    int v2_ = o & 1;
                    const float4* thp = (const float4*)&th_s[(size_t)(pos + i) * 8];
                    float4 t0 = thp[0], t1 = thp[1];
                    float th8[8] = { t0.x, t0.y, t0.z, t0.w,
                                     t1.x, t1.y, t1.z, t1.w };
                    unsigned newbits = 0;
                    float dv[8];
#define DEC_O(V)                                                              \
                    {                                                         \
                        _Pragma("unroll")                                     \
                        for (int p = 0; p < 4; p++) {                         \
                            ull g = rO[V][p];                                 \
                            float glo = __uint_as_float((unsigned)g);         \
                            float ghi = __uint_as_float((unsigned)(g >> 32)); \
                            float nl = (glo > th8[2 * p])     ? 1.f : 0.f;    \
                            float nh = (ghi > th8[2 * p + 1]) ? 1.f : 0.f;    \
                            if (nl > 0.f) newbits |= 1u << (2 * p);           \
                            if (nh > 0.f) newbits |= 1u << (2 * p + 1);       \
                            dv[2 * p] = nl; dv[2 * p + 1] = nh;               \
                        }                                                     \
                    }
                    if (v2_ == 0) DEC_O(0) else DEC_O(1)
#undef DEC_O
                    unsigned oldb = (sO >> (v2_ * 8)) & 0xFFu;
#pragma unroll
                    for (int c = 0; c < 8; c++)
                        dv[c] -= (float)((oldb >> c) & 1u);
                    sO = (sO & ~(0xFFu << (v2_ * 8))) | (newbits << (v2_ * 8));
                    float4* dq = (float4*)(dbase + i * 8);
                    dq[0] = make_float4(dv[0], dv[1], dv[2], dv[3]);
                    dq[1] = make_float4(dv[4], dv[5], dv[6], dv[7]);
                }
            }
        }
        __syncthreads();

        // ---- apply (all threads, register FMAs) ----
        if (!lay) {
            for (int i = 0; i < r; i++) {
                int n = ids_s[pos + i];
                float2 wv = __ldg((const float2*)(g_W2T + (size_t)n * NOUT + 2 * tid));
                ull w0 = pack2f(wv.x, wv.x);
                ull w1 = pack2f(wv.y, wv.y);
                const ull* dp = (const ull*)(dbase + i * 8);
#pragma unroll
                for (int p = 0; p < 4; p++) {
                    ull d = dp[p];
                    fma2(rO[0][p], d, w0);
                    fma2(rO[1][p], d, w1);
                }
            }
        } else {
            for (int i = 0; i < r; i++) {
                int o = ids_s[pos + i] - NH;
                float4 wv = __ldg((const float4*)(W2 + (size_t)o * NH + 4 * tid));
                ull w0 = pack2f(wv.x, wv.x);
                ull w1 = pack2f(wv.y, wv.y);
                ull w2_ = pack2f(wv.z, wv.z);
                ull w3 = pack2f(wv.w, wv.w);
                const ull* dp = (const ull*)(dbase + i * 8);
#pragma unroll
                for (int p = 0; p < 4; p++) {
                    ull d = dp[p];
                    fma2(rH[0][p], d, w0);
                    fma2(rH[1][p], d, w1);
                    fma2(rH[2][p], d, w2_);
                    fma2(rH[3][p], d, w3);
                }
            }
        }
        pos += r;
        buf ^= 1;
    }

    // ---- epilogue: direct coalesced writes from registers ----
#pragma unroll
    for (int c = 0; c < 8; c++) {
        int b = c0 + c;
        size_t rb4 = (size_t)b * 640;
        ((float4*)out)[rb4 + tid] = ((const float4*)x)[(size_t)b * 256 + tid];
        float4 s1v;
        s1v.x = (sH >> (0 * 8 + c)) & 1u ? 1.f : 0.f;
        s1v.y = (sH >> (1 * 8 + c)) & 1u ? 1.f : 0.f;
        s1v.z = (sH >> (2 * 8 + c)) & 1u ? 1.f : 0.f;
        s1v.w = (sH >> (3 * 8 + c)) & 1u ? 1.f : 0.f;
        ((float4*)out)[rb4 + 256 + tid] = s1v;
        float2 s2v;
        s2v.x = (sO >> (0 * 8 + c)) & 1u ? 1.f : 0.f;
        s2v.y = (sO >> (1 * 8 + c)) & 1u ? 1.f : 0.f;
        *(float2*)&out[(size_t)b * 2560 + 2048 + 2 * tid] = s2v;
    }
}

// ---------------------------------------------------------------------------
extern "C" void kernel_launch(void* const* d_in, const int* in_sizes, int n_in,
                              void* d_out, int out_size)
{
    const float* x   = (const float*)d_in[0];
    const float* s1i = (const float*)d_in[1];
    const float* s2i = (const float*)d_in[2];
    const float* W1  = (const float*)d_in[3];
    const float* b1  = (const float*)d_in[4];
    const float* W2  = (const float*)d_in[5];
    const float* b2  = (const float*)d_in[6];
    const float* u   = (const float*)d_in[7];
    const int*   ids = (const int*)d_in[8];
    float* out = (float*)d_out;

    float *pA, *pWH, *pW2T, *pGH, *pGO;
    cudaGetSymbolAddress((void**)&pA,   g_A);
    cudaGetSymbolAddress((void**)&pWH,  g_WH);
    cudaGetSymbolAddress((void**)&pW2T, g_W2T);
    cudaGetSymbolAddress((void**)&pGH,  g_gapH);
    cudaGetSymbolAddress((void**)&pGO,  g_gapO);

    prep_k     <<<29696, 256>>>(x, s2i, W1, W2, u);
    gemm_bias_k<<<dim3(16, 16), 256>>>(pA,  pWH,  b1, pGH, 2048, 1024, 1536);
    gemm_bias_k<<<dim3(8, 16),  256>>>(s1i, pW2T, b2, pGO, 2048, 512, 1024);

    cudaFuncSetAttribute(gibbs_k, cudaFuncAttributeMaxDynamicSharedMemorySize,
                         SMEM_BYTES);
    gibbs_k<<<256, 256, SMEM_BYTES>>>(x, s1i, s2i, W2, ids, out);
}